// round 9
// baseline (speedup 1.0000x reference)
#include <cuda_runtime.h>
#include <cuda_bf16.h>
#include <cstdint>

// SurfNetwork fused kernel, warp-per-ray + L2 evict_last policy on gathers.
// B rays, N=128 samples/ray. One warp per ray, 4 samples per lane.
// Gathers use createpolicy + ld.global.nc.L2::cache_hint.v4.f32 (the static
// .L2::evict_last qualifier requires 256-bit loads on sm_100; the cache_hint
// form works at 128-bit). Fraction 0.5 so the protected set fits in L2.
//
// Inputs (metadata order):
//   d_in[0] x          int32  [B, N, 2]
//   d_in[1] d          f32    [B, 16]
//   d_in[2] gridWeight f32    [TABLE, 4]
//   d_in[3] W0         f32    [22, 8]
//   d_in[4] W1         f32    [8, 3]
// Output: d_out = [ sigma (B*N f32) | rgb (B*3 f32) ]

__device__ __forceinline__ float fast_sigmoid(float z) {
    return 1.0f / (1.0f + __expf(-z));
}

// float4 gather with L2 cache-policy hint (keep table rows resident).
__device__ __forceinline__ float4 ldg_keep(const float4* p, uint64_t pol) {
    float4 v;
    asm volatile("ld.global.nc.L2::cache_hint.v4.f32 {%0,%1,%2,%3}, [%4], %5;"
                 : "=f"(v.x), "=f"(v.y), "=f"(v.z), "=f"(v.w)
                 : "l"(p), "l"(pol));
    return v;
}

__device__ __forceinline__ void mlp_color(
    const float4 fa, const float4 fb,
    const float* __restrict__ basev,   // [8] regs
    const float* __restrict__ sW0g,    // [6][8] shared
    const float* __restrict__ sW1,     // [8][3] shared
    float& c0, float& c1, float& c2)
{
    float h[8];
    #pragma unroll
    for (int j = 0; j < 8; j++) {
        float v = basev[j];
        v = fmaf(fa.y, sW0g[0 * 8 + j], v);
        v = fmaf(fa.z, sW0g[1 * 8 + j], v);
        v = fmaf(fa.w, sW0g[2 * 8 + j], v);
        v = fmaf(fb.y, sW0g[3 * 8 + j], v);
        v = fmaf(fb.z, sW0g[4 * 8 + j], v);
        v = fmaf(fb.w, sW0g[5 * 8 + j], v);
        h[j] = fmaxf(v, 0.0f);
    }
    c0 = 0.f; c1 = 0.f; c2 = 0.f;
    #pragma unroll
    for (int j = 0; j < 8; j++) {
        c0 = fmaf(h[j], sW1[j * 3 + 0], c0);
        c1 = fmaf(h[j], sW1[j * 3 + 1], c1);
        c2 = fmaf(h[j], sW1[j * 3 + 2], c2);
    }
    c0 = fast_sigmoid(c0);
    c1 = fast_sigmoid(c1);
    c2 = fast_sigmoid(c2);
}

__global__ __launch_bounds__(128) void surfnet_kernel(
    const int*   __restrict__ x,        // [B, N, 2]
    const float* __restrict__ dvec,     // [B, 16]
    const float* __restrict__ grid,     // [TABLE, 4]
    const float* __restrict__ W0,       // [22, 8]
    const float* __restrict__ W1,       // [8, 3]
    float*       __restrict__ sigma_out,// [B, N]
    float*       __restrict__ rgb_out,  // [B, 3]
    int B)
{
    const int tid  = threadIdx.x;
    const int lane = tid & 31;
    const int wid  = tid >> 5;

    __shared__ float sW0g[48];  // W0 rows 16..21, [6][8]
    __shared__ float sW1[24];   // [8][3]

    if (tid < 48)      sW0g[tid]      = W0[128 + tid];   // 16*8 = 128
    else if (tid < 72) sW1[tid - 48]  = W1[tid - 48];
    __syncthreads();

    const int b = blockIdx.x * 4 + wid;   // ray index (one warp per ray)
    if (b >= B) return;

    // L2 access policy: half of gather accesses marked evict_last so the
    // protected set (~L2/2) actually fits and persists.
    uint64_t pol;
    asm volatile("createpolicy.fractional.L2::evict_last.b64 %0, 0.5;" : "=l"(pol));

    // per-ray base = d[b] @ W0[0:16,:], computed by lanes 0..7, broadcast
    float base = 0.0f;
    if (lane < 8) {
        const float* dv = dvec + (size_t)b * 16;
        #pragma unroll
        for (int i = 0; i < 16; i++)
            base = fmaf(__ldg(dv + i), __ldg(W0 + i * 8 + lane), base);
    }
    float basev[8];
    #pragma unroll
    for (int j = 0; j < 8; j++)
        basev[j] = __shfl_sync(0xFFFFFFFFu, base, j);

    // ---- gather: 4 consecutive samples per lane -> 8 float4 loads in flight
    const int4* xp = (const int4*)x + (size_t)b * 64 + lane * 2;  // b*256 ints
    const int4 xa = __ldcs(xp);        // {s0.x, s0.y, s1.x, s1.y}
    const int4 xb = __ldcs(xp + 1);    // {s2.x, s2.y, s3.x, s3.y}

    const float4* g4 = (const float4*)grid;
    const float4 fa0 = ldg_keep(g4 + xa.x, pol), fb0 = ldg_keep(g4 + xa.y, pol);
    const float4 fa1 = ldg_keep(g4 + xa.z, pol), fb1 = ldg_keep(g4 + xa.w, pol);
    const float4 fa2 = ldg_keep(g4 + xb.x, pol), fb2 = ldg_keep(g4 + xb.y, pol);
    const float4 fa3 = ldg_keep(g4 + xb.z, pol), fb3 = ldg_keep(g4 + xb.w, pol);

    float sg[4];
    sg[0] = fast_sigmoid(fa0.x * fb0.x);
    sg[1] = fast_sigmoid(fa1.x * fb1.x);
    sg[2] = fast_sigmoid(fa2.x * fb2.x);
    sg[3] = fast_sigmoid(fa3.x * fb3.x);

    // coalesced sigma store: 4 consecutive samples = one float4 per lane
    __stcs((float4*)(sigma_out + (size_t)b * 128) + lane,
           make_float4(sg[0], sg[1], sg[2], sg[3]));

    float ca[4], cb[4], cc[4];
    mlp_color(fa0, fb0, basev, sW0g, sW1, ca[0], cb[0], cc[0]);
    mlp_color(fa1, fb1, basev, sW0g, sW1, ca[1], cb[1], cc[1]);
    mlp_color(fa2, fb2, basev, sW0g, sW1, ca[2], cb[2], cc[2]);
    mlp_color(fa3, fb3, basev, sW0g, sW1, ca[3], cb[3], cc[3]);

    // ---- transmittance: serial product within lane, shuffle scan across lanes
    const float om0 = 1.0f - sg[0], om1 = 1.0f - sg[1];
    const float om2 = 1.0f - sg[2], om3 = 1.0f - sg[3];
    float incl = om0 * om1 * om2 * om3;
    #pragma unroll
    for (int off = 1; off < 32; off <<= 1) {
        float v = __shfl_up_sync(0xFFFFFFFFu, incl, off);
        if (lane >= off) incl *= v;
    }
    float T = __shfl_up_sync(0xFFFFFFFFu, incl, 1);
    if (lane == 0) T = 1.0f;

    float r0 = 0.f, r1 = 0.f, r2 = 0.f;
    float w;
    w = T * sg[0]; r0 = fmaf(w, ca[0], r0); r1 = fmaf(w, cb[0], r1); r2 = fmaf(w, cc[0], r2); T *= om0;
    w = T * sg[1]; r0 = fmaf(w, ca[1], r0); r1 = fmaf(w, cb[1], r1); r2 = fmaf(w, cc[1], r2); T *= om1;
    w = T * sg[2]; r0 = fmaf(w, ca[2], r0); r1 = fmaf(w, cb[2], r1); r2 = fmaf(w, cc[2], r2); T *= om2;
    w = T * sg[3]; r0 = fmaf(w, ca[3], r0); r1 = fmaf(w, cb[3], r1); r2 = fmaf(w, cc[3], r2);

    #pragma unroll
    for (int off = 16; off > 0; off >>= 1) {
        r0 += __shfl_down_sync(0xFFFFFFFFu, r0, off);
        r1 += __shfl_down_sync(0xFFFFFFFFu, r1, off);
        r2 += __shfl_down_sync(0xFFFFFFFFu, r2, off);
    }
    if (lane == 0) {
        float* rb = rgb_out + (size_t)b * 3;
        rb[0] = r0; rb[1] = r1; rb[2] = r2;
    }
}

extern "C" void kernel_launch(void* const* d_in, const int* in_sizes, int n_in,
                              void* d_out, int out_size)
{
    const int*   x    = (const int*)d_in[0];
    const float* dv   = (const float*)d_in[1];
    const float* grid = (const float*)d_in[2];
    const float* W0   = (const float*)d_in[3];
    const float* W1   = (const float*)d_in[4];

    const int BN = in_sizes[0] / 2;   // B*N
    const int B  = in_sizes[1] / 16;  // rays

    float* sigma_out = (float*)d_out;
    float* rgb_out   = sigma_out + (size_t)BN;

    const int nblk = (B + 3) / 4;
    surfnet_kernel<<<nblk, 128>>>(x, dv, grid, W0, W1, sigma_out, rgb_out, B);
}

// round 10
// speedup vs baseline: 1.0203x; 1.0203x over previous
#include <cuda_runtime.h>
#include <cuda_bf16.h>
#include <cstdint>

// SurfNetwork fused kernel, warp-per-ray; gathers via ld.global.cg (L2-only,
// bypass L1/texture path) to avoid full-line (128B) fetch promotion on the
// random 16B table reads. B rays, N=128 samples/ray, one warp per ray,
// 4 samples per lane (8 gathers in flight per thread).
//
// Inputs (metadata order):
//   d_in[0] x          int32  [B, N, 2]
//   d_in[1] d          f32    [B, 16]
//   d_in[2] gridWeight f32    [TABLE, 4]
//   d_in[3] W0         f32    [22, 8]
//   d_in[4] W1         f32    [8, 3]
// Output: d_out = [ sigma (B*N f32) | rgb (B*3 f32) ]

__device__ __forceinline__ float fast_sigmoid(float z) {
    return 1.0f / (1.0f + __expf(-z));
}

// float4 gather, L2-only caching (no L1 allocation, sector-granular fetch).
__device__ __forceinline__ float4 ldg_cg(const float4* p) {
    float4 v;
    asm volatile("ld.global.cg.v4.f32 {%0,%1,%2,%3}, [%4];"
                 : "=f"(v.x), "=f"(v.y), "=f"(v.z), "=f"(v.w)
                 : "l"(p));
    return v;
}

__device__ __forceinline__ void mlp_color(
    const float4 fa, const float4 fb,
    const float* __restrict__ basev,   // [8] regs
    const float* __restrict__ sW0g,    // [6][8] shared
    const float* __restrict__ sW1,     // [8][3] shared
    float& c0, float& c1, float& c2)
{
    float h[8];
    #pragma unroll
    for (int j = 0; j < 8; j++) {
        float v = basev[j];
        v = fmaf(fa.y, sW0g[0 * 8 + j], v);
        v = fmaf(fa.z, sW0g[1 * 8 + j], v);
        v = fmaf(fa.w, sW0g[2 * 8 + j], v);
        v = fmaf(fb.y, sW0g[3 * 8 + j], v);
        v = fmaf(fb.z, sW0g[4 * 8 + j], v);
        v = fmaf(fb.w, sW0g[5 * 8 + j], v);
        h[j] = fmaxf(v, 0.0f);
    }
    c0 = 0.f; c1 = 0.f; c2 = 0.f;
    #pragma unroll
    for (int j = 0; j < 8; j++) {
        c0 = fmaf(h[j], sW1[j * 3 + 0], c0);
        c1 = fmaf(h[j], sW1[j * 3 + 1], c1);
        c2 = fmaf(h[j], sW1[j * 3 + 2], c2);
    }
    c0 = fast_sigmoid(c0);
    c1 = fast_sigmoid(c1);
    c2 = fast_sigmoid(c2);
}

__global__ __launch_bounds__(128) void surfnet_kernel(
    const int*   __restrict__ x,        // [B, N, 2]
    const float* __restrict__ dvec,     // [B, 16]
    const float* __restrict__ grid,     // [TABLE, 4]
    const float* __restrict__ W0,       // [22, 8]
    const float* __restrict__ W1,       // [8, 3]
    float*       __restrict__ sigma_out,// [B, N]
    float*       __restrict__ rgb_out,  // [B, 3]
    int B)
{
    const int tid  = threadIdx.x;
    const int lane = tid & 31;
    const int wid  = tid >> 5;

    __shared__ float sW0g[48];  // W0 rows 16..21, [6][8]
    __shared__ float sW1[24];   // [8][3]

    if (tid < 48)      sW0g[tid]      = W0[128 + tid];   // 16*8 = 128
    else if (tid < 72) sW1[tid - 48]  = W1[tid - 48];
    __syncthreads();

    const int b = blockIdx.x * 4 + wid;   // ray index (one warp per ray)
    if (b >= B) return;

    // per-ray base = d[b] @ W0[0:16,:], computed by lanes 0..7, broadcast
    float base = 0.0f;
    if (lane < 8) {
        const float* dv = dvec + (size_t)b * 16;
        #pragma unroll
        for (int i = 0; i < 16; i++)
            base = fmaf(__ldg(dv + i), __ldg(W0 + i * 8 + lane), base);
    }
    float basev[8];
    #pragma unroll
    for (int j = 0; j < 8; j++)
        basev[j] = __shfl_sync(0xFFFFFFFFu, base, j);

    // ---- gather: 4 consecutive samples per lane -> 8 float4 loads in flight
    const int4* xp = (const int4*)x + (size_t)b * 64 + lane * 2;  // b*256 ints
    const int4 xa = __ldcs(xp);        // {s0.x, s0.y, s1.x, s1.y}
    const int4 xb = __ldcs(xp + 1);    // {s2.x, s2.y, s3.x, s3.y}

    const float4* g4 = (const float4*)grid;
    const float4 fa0 = ldg_cg(g4 + xa.x), fb0 = ldg_cg(g4 + xa.y);
    const float4 fa1 = ldg_cg(g4 + xa.z), fb1 = ldg_cg(g4 + xa.w);
    const float4 fa2 = ldg_cg(g4 + xb.x), fb2 = ldg_cg(g4 + xb.y);
    const float4 fa3 = ldg_cg(g4 + xb.z), fb3 = ldg_cg(g4 + xb.w);

    float sg[4];
    sg[0] = fast_sigmoid(fa0.x * fb0.x);
    sg[1] = fast_sigmoid(fa1.x * fb1.x);
    sg[2] = fast_sigmoid(fa2.x * fb2.x);
    sg[3] = fast_sigmoid(fa3.x * fb3.x);

    // coalesced sigma store: 4 consecutive samples = one float4 per lane
    __stcs((float4*)(sigma_out + (size_t)b * 128) + lane,
           make_float4(sg[0], sg[1], sg[2], sg[3]));

    float ca[4], cb[4], cc[4];
    mlp_color(fa0, fb0, basev, sW0g, sW1, ca[0], cb[0], cc[0]);
    mlp_color(fa1, fb1, basev, sW0g, sW1, ca[1], cb[1], cc[1]);
    mlp_color(fa2, fb2, basev, sW0g, sW1, ca[2], cb[2], cc[2]);
    mlp_color(fa3, fb3, basev, sW0g, sW1, ca[3], cb[3], cc[3]);

    // ---- transmittance: serial product within lane, shuffle scan across lanes
    const float om0 = 1.0f - sg[0], om1 = 1.0f - sg[1];
    const float om2 = 1.0f - sg[2], om3 = 1.0f - sg[3];
    float incl = om0 * om1 * om2 * om3;
    #pragma unroll
    for (int off = 1; off < 32; off <<= 1) {
        float v = __shfl_up_sync(0xFFFFFFFFu, incl, off);
        if (lane >= off) incl *= v;
    }
    float T = __shfl_up_sync(0xFFFFFFFFu, incl, 1);
    if (lane == 0) T = 1.0f;

    float r0 = 0.f, r1 = 0.f, r2 = 0.f;
    float w;
    w = T * sg[0]; r0 = fmaf(w, ca[0], r0); r1 = fmaf(w, cb[0], r1); r2 = fmaf(w, cc[0], r2); T *= om0;
    w = T * sg[1]; r0 = fmaf(w, ca[1], r0); r1 = fmaf(w, cb[1], r1); r2 = fmaf(w, cc[1], r2); T *= om1;
    w = T * sg[2]; r0 = fmaf(w, ca[2], r0); r1 = fmaf(w, cb[2], r1); r2 = fmaf(w, cc[2], r2); T *= om2;
    w = T * sg[3]; r0 = fmaf(w, ca[3], r0); r1 = fmaf(w, cb[3], r1); r2 = fmaf(w, cc[3], r2);

    #pragma unroll
    for (int off = 16; off > 0; off >>= 1) {
        r0 += __shfl_down_sync(0xFFFFFFFFu, r0, off);
        r1 += __shfl_down_sync(0xFFFFFFFFu, r1, off);
        r2 += __shfl_down_sync(0xFFFFFFFFu, r2, off);
    }
    if (lane == 0) {
        float* rb = rgb_out + (size_t)b * 3;
        rb[0] = r0; rb[1] = r1; rb[2] = r2;
    }
}

extern "C" void kernel_launch(void* const* d_in, const int* in_sizes, int n_in,
                              void* d_out, int out_size)
{
    const int*   x    = (const int*)d_in[0];
    const float* dv   = (const float*)d_in[1];
    const float* grid = (const float*)d_in[2];
    const float* W0   = (const float*)d_in[3];
    const float* W1   = (const float*)d_in[4];

    const int BN = in_sizes[0] / 2;   // B*N
    const int B  = in_sizes[1] / 16;  // rays

    float* sigma_out = (float*)d_out;
    float* rgb_out   = sigma_out + (size_t)BN;

    const int nblk = (B + 3) / 4;
    surfnet_kernel<<<nblk, 128>>>(x, dv, grid, W0, W1, sigma_out, rgb_out, B);
}

// round 11
// speedup vs baseline: 1.0330x; 1.0124x over previous
#include <cuda_runtime.h>
#include <cuda_bf16.h>
#include <cstdint>

// SurfNetwork fused kernel, warp-per-ray; gathers via ld.global.cg (L2-only,
// bypass L1/texture path) to avoid full-line (128B) fetch promotion on the
// random 16B table reads. B rays, N=128 samples/ray, one warp per ray,
// 4 samples per lane (8 gathers in flight per thread).
//
// Inputs (metadata order):
//   d_in[0] x          int32  [B, N, 2]
//   d_in[1] d          f32    [B, 16]
//   d_in[2] gridWeight f32    [TABLE, 4]
//   d_in[3] W0         f32    [22, 8]
//   d_in[4] W1         f32    [8, 3]
// Output: d_out = [ sigma (B*N f32) | rgb (B*3 f32) ]

__device__ __forceinline__ float fast_sigmoid(float z) {
    return 1.0f / (1.0f + __expf(-z));
}

// float4 gather, L2-only caching (no L1 allocation, sector-granular fetch).
__device__ __forceinline__ float4 ldg_cg(const float4* p) {
    float4 v;
    asm volatile("ld.global.cg.v4.f32 {%0,%1,%2,%3}, [%4];"
                 : "=f"(v.x), "=f"(v.y), "=f"(v.z), "=f"(v.w)
                 : "l"(p));
    return v;
}

__device__ __forceinline__ void mlp_color(
    const float4 fa, const float4 fb,
    const float* __restrict__ basev,   // [8] regs
    const float* __restrict__ sW0g,    // [6][8] shared
    const float* __restrict__ sW1,     // [8][3] shared
    float& c0, float& c1, float& c2)
{
    float h[8];
    #pragma unroll
    for (int j = 0; j < 8; j++) {
        float v = basev[j];
        v = fmaf(fa.y, sW0g[0 * 8 + j], v);
        v = fmaf(fa.z, sW0g[1 * 8 + j], v);
        v = fmaf(fa.w, sW0g[2 * 8 + j], v);
        v = fmaf(fb.y, sW0g[3 * 8 + j], v);
        v = fmaf(fb.z, sW0g[4 * 8 + j], v);
        v = fmaf(fb.w, sW0g[5 * 8 + j], v);
        h[j] = fmaxf(v, 0.0f);
    }
    c0 = 0.f; c1 = 0.f; c2 = 0.f;
    #pragma unroll
    for (int j = 0; j < 8; j++) {
        c0 = fmaf(h[j], sW1[j * 3 + 0], c0);
        c1 = fmaf(h[j], sW1[j * 3 + 1], c1);
        c2 = fmaf(h[j], sW1[j * 3 + 2], c2);
    }
    c0 = fast_sigmoid(c0);
    c1 = fast_sigmoid(c1);
    c2 = fast_sigmoid(c2);
}

__global__ __launch_bounds__(128) void surfnet_kernel(
    const int*   __restrict__ x,        // [B, N, 2]
    const float* __restrict__ dvec,     // [B, 16]
    const float* __restrict__ grid,     // [TABLE, 4]
    const float* __restrict__ W0,       // [22, 8]
    const float* __restrict__ W1,       // [8, 3]
    float*       __restrict__ sigma_out,// [B, N]
    float*       __restrict__ rgb_out,  // [B, 3]
    int B)
{
    const int tid  = threadIdx.x;
    const int lane = tid & 31;
    const int wid  = tid >> 5;

    __shared__ float sW0g[48];  // W0 rows 16..21, [6][8]
    __shared__ float sW1[24];   // [8][3]

    if (tid < 48)      sW0g[tid]      = W0[128 + tid];   // 16*8 = 128
    else if (tid < 72) sW1[tid - 48]  = W1[tid - 48];
    __syncthreads();

    const int b = blockIdx.x * 4 + wid;   // ray index (one warp per ray)
    if (b >= B) return;

    // per-ray base = d[b] @ W0[0:16,:], computed by lanes 0..7, broadcast
    float base = 0.0f;
    if (lane < 8) {
        const float* dv = dvec + (size_t)b * 16;
        #pragma unroll
        for (int i = 0; i < 16; i++)
            base = fmaf(__ldg(dv + i), __ldg(W0 + i * 8 + lane), base);
    }
    float basev[8];
    #pragma unroll
    for (int j = 0; j < 8; j++)
        basev[j] = __shfl_sync(0xFFFFFFFFu, base, j);

    // ---- gather: 4 consecutive samples per lane -> 8 float4 loads in flight
    const int4* xp = (const int4*)x + (size_t)b * 64 + lane * 2;  // b*256 ints
    const int4 xa = __ldcs(xp);        // {s0.x, s0.y, s1.x, s1.y}
    const int4 xb = __ldcs(xp + 1);    // {s2.x, s2.y, s3.x, s3.y}

    const float4* g4 = (const float4*)grid;
    const float4 fa0 = ldg_cg(g4 + xa.x), fb0 = ldg_cg(g4 + xa.y);
    const float4 fa1 = ldg_cg(g4 + xa.z), fb1 = ldg_cg(g4 + xa.w);
    const float4 fa2 = ldg_cg(g4 + xb.x), fb2 = ldg_cg(g4 + xb.y);
    const float4 fa3 = ldg_cg(g4 + xb.z), fb3 = ldg_cg(g4 + xb.w);

    float sg[4];
    sg[0] = fast_sigmoid(fa0.x * fb0.x);
    sg[1] = fast_sigmoid(fa1.x * fb1.x);
    sg[2] = fast_sigmoid(fa2.x * fb2.x);
    sg[3] = fast_sigmoid(fa3.x * fb3.x);

    // coalesced sigma store: 4 consecutive samples = one float4 per lane
    __stcs((float4*)(sigma_out + (size_t)b * 128) + lane,
           make_float4(sg[0], sg[1], sg[2], sg[3]));

    float ca[4], cb[4], cc[4];
    mlp_color(fa0, fb0, basev, sW0g, sW1, ca[0], cb[0], cc[0]);
    mlp_color(fa1, fb1, basev, sW0g, sW1, ca[1], cb[1], cc[1]);
    mlp_color(fa2, fb2, basev, sW0g, sW1, ca[2], cb[2], cc[2]);
    mlp_color(fa3, fb3, basev, sW0g, sW1, ca[3], cb[3], cc[3]);

    // ---- transmittance: serial product within lane, shuffle scan across lanes
    const float om0 = 1.0f - sg[0], om1 = 1.0f - sg[1];
    const float om2 = 1.0f - sg[2], om3 = 1.0f - sg[3];
    float incl = om0 * om1 * om2 * om3;
    #pragma unroll
    for (int off = 1; off < 32; off <<= 1) {
        float v = __shfl_up_sync(0xFFFFFFFFu, incl, off);
        if (lane >= off) incl *= v;
    }
    float T = __shfl_up_sync(0xFFFFFFFFu, incl, 1);
    if (lane == 0) T = 1.0f;

    float r0 = 0.f, r1 = 0.f, r2 = 0.f;
    float w;
    w = T * sg[0]; r0 = fmaf(w, ca[0], r0); r1 = fmaf(w, cb[0], r1); r2 = fmaf(w, cc[0], r2); T *= om0;
    w = T * sg[1]; r0 = fmaf(w, ca[1], r0); r1 = fmaf(w, cb[1], r1); r2 = fmaf(w, cc[1], r2); T *= om1;
    w = T * sg[2]; r0 = fmaf(w, ca[2], r0); r1 = fmaf(w, cb[2], r1); r2 = fmaf(w, cc[2], r2); T *= om2;
    w = T * sg[3]; r0 = fmaf(w, ca[3], r0); r1 = fmaf(w, cb[3], r1); r2 = fmaf(w, cc[3], r2);

    #pragma unroll
    for (int off = 16; off > 0; off >>= 1) {
        r0 += __shfl_down_sync(0xFFFFFFFFu, r0, off);
        r1 += __shfl_down_sync(0xFFFFFFFFu, r1, off);
        r2 += __shfl_down_sync(0xFFFFFFFFu, r2, off);
    }
    if (lane == 0) {
        float* rb = rgb_out + (size_t)b * 3;
        rb[0] = r0; rb[1] = r1; rb[2] = r2;
    }
}

extern "C" void kernel_launch(void* const* d_in, const int* in_sizes, int n_in,
                              void* d_out, int out_size)
{
    const int*   x    = (const int*)d_in[0];
    const float* dv   = (const float*)d_in[1];
    const float* grid = (const float*)d_in[2];
    const float* W0   = (const float*)d_in[3];
    const float* W1   = (const float*)d_in[4];

    const int BN = in_sizes[0] / 2;   // B*N
    const int B  = in_sizes[1] / 16;  // rays

    float* sigma_out = (float*)d_out;
    float* rgb_out   = sigma_out + (size_t)BN;

    const int nblk = (B + 3) / 4;
    surfnet_kernel<<<nblk, 128>>>(x, dv, grid, W0, W1, sigma_out, rgb_out, B);
}